// round 2
// baseline (speedup 1.0000x reference)
#include <cuda_runtime.h>
#include <math.h>

#define BATCH   16
#define CH      512
#define HW_     1024          // tokens N
#define NGROUPS 8
#define CG      (CH/NGROUPS)  // 64 channels per group
#define NH      8
#define HD      64            // head dim
#define EPS_    1e-5f
#define SCALE_  0.125f        // 64^-0.5

// Scratch (allocation-free): 32MB + 96MB + 32MB
__device__ float g_xn [BATCH*CH*HW_];
__device__ float g_qkv[(size_t)BATCH*3*CH*HW_];
__device__ float g_att[BATCH*CH*HW_];

// ---------------------------------------------------------------------------
// GroupNorm: one block per (batch, group); 64ch x 1024 = 65536 elems/group
// ---------------------------------------------------------------------------
__global__ void groupnorm_kernel(const float* __restrict__ x,
                                 const float* __restrict__ w,
                                 const float* __restrict__ bias,
                                 float* __restrict__ xn)
{
    int bg = blockIdx.x;
    int bb = bg / NGROUPS, g = bg % NGROUPS;
    const float* xp = x  + ((size_t)bb*CH + g*CG) * HW_;
    float*       op = xn + ((size_t)bb*CH + g*CG) * HW_;
    const int NEL = CG * HW_;  // 65536
    int tid = threadIdx.x;

    float s = 0.f, ss = 0.f;
    for (int i = tid*4; i < NEL; i += blockDim.x*4) {
        float4 v = *(const float4*)&xp[i];
        s  += v.x + v.y + v.z + v.w;
        ss += v.x*v.x + v.y*v.y + v.z*v.z + v.w*v.w;
    }
    __shared__ float r1[256], r2[256];
    r1[tid] = s; r2[tid] = ss;
    __syncthreads();
    for (int st = 128; st > 0; st >>= 1) {
        if (tid < st) { r1[tid] += r1[tid+st]; r2[tid] += r2[tid+st]; }
        __syncthreads();
    }
    float mean = r1[0] * (1.f/NEL);
    float var  = r2[0] * (1.f/NEL) - mean*mean;
    float inv  = rsqrtf(var + EPS_);

    for (int i = tid*4; i < NEL; i += blockDim.x*4) {
        int ch = g*CG + (i >> 10);   // same channel across the float4 (1024 | i)
        float wc = w[ch], bc = bias[ch];
        float4 v = *(const float4*)&xp[i];
        float4 o;
        o.x = (v.x - mean)*inv*wc + bc;
        o.y = (v.y - mean)*inv*wc + bc;
        o.z = (v.z - mean)*inv*wc + bc;
        o.w = (v.w - mean)*inv*wc + bc;
        *(float4*)&op[i] = o;
    }
}

// ---------------------------------------------------------------------------
// SGEMM: C[bz] = A[MxK] * B[bz][KxN] + bias (+ optional residual R[bz])
// 128x128 tile, BK=8, 256 threads, 8x8 microtile. All dims multiples of tile.
// ---------------------------------------------------------------------------
__global__ void sgemm_kernel(const float* __restrict__ A,
                             const float* __restrict__ Bbase,
                             float* __restrict__ Cbase,
                             const float* __restrict__ bias,
                             const float* __restrict__ Rbase,
                             int M, int K, int N)
{
    __shared__ float As[8][132];   // padded, stored transposed: As[k][m]
    __shared__ float Bs[8][128];   // Bs[k][n]

    int bz = blockIdx.z;
    const float* Bm = Bbase + (size_t)bz * K * N;
    float*       Cm = Cbase + (size_t)bz * M * N;
    const float* Rm = Rbase ? (Rbase + (size_t)bz * M * N) : (const float*)0;

    int m0 = blockIdx.y * 128, n0 = blockIdx.x * 128;
    int tid  = threadIdx.x;
    int arow = tid >> 1, acol = (tid & 1) * 4;
    int brow = tid >> 5, bcol = (tid & 31) * 4;
    int ty = tid >> 4, tx = tid & 15;

    float acc[8][8];
    #pragma unroll
    for (int i = 0; i < 8; i++)
        #pragma unroll
        for (int j = 0; j < 8; j++) acc[i][j] = 0.f;

    for (int k0 = 0; k0 < K; k0 += 8) {
        float4 av = *(const float4*)&A[(size_t)(m0+arow)*K + k0 + acol];
        As[acol+0][arow] = av.x;
        As[acol+1][arow] = av.y;
        As[acol+2][arow] = av.z;
        As[acol+3][arow] = av.w;
        *(float4*)&Bs[brow][bcol] = *(const float4*)&Bm[(size_t)(k0+brow)*N + n0 + bcol];
        __syncthreads();

        #pragma unroll
        for (int k = 0; k < 8; k++) {
            float a[8], bv[8];
            *(float4*)&a[0]  = *(const float4*)&As[k][ty*4];
            *(float4*)&a[4]  = *(const float4*)&As[k][64 + ty*4];
            *(float4*)&bv[0] = *(const float4*)&Bs[k][tx*4];
            *(float4*)&bv[4] = *(const float4*)&Bs[k][64 + tx*4];
            #pragma unroll
            for (int i = 0; i < 8; i++)
                #pragma unroll
                for (int j = 0; j < 8; j++)
                    acc[i][j] += a[i] * bv[j];
        }
        __syncthreads();
    }

    #pragma unroll
    for (int i = 0; i < 8; i++) {
        int m = m0 + ((i < 4) ? (ty*4 + i) : (64 + ty*4 + i - 4));
        float bvv = bias ? bias[m] : 0.f;
        #pragma unroll
        for (int jg = 0; jg < 2; jg++) {
            int n = n0 + ((jg == 0) ? tx*4 : 64 + tx*4);
            float4 o;
            o.x = acc[i][jg*4+0] + bvv;
            o.y = acc[i][jg*4+1] + bvv;
            o.z = acc[i][jg*4+2] + bvv;
            o.w = acc[i][jg*4+3] + bvv;
            if (Rm) {
                float4 r = *(const float4*)&Rm[(size_t)m*N + n];
                o.x += r.x; o.y += r.y; o.z += r.z; o.w += r.w;
            }
            *(float4*)&Cm[(size_t)m*N + n] = o;
        }
    }
}

// ---------------------------------------------------------------------------
// Flash attention: block = 64 queries of one (b,h); online softmax over 16
// key tiles of 64. qkv layout: [b][3c][n]; Q/K/V stored d-major (stride N).
// ---------------------------------------------------------------------------
__global__ void attention_kernel(const float* __restrict__ qkv,
                                 float* __restrict__ outp)
{
    extern __shared__ float sm[];
    float* Qs = sm;            // [64][64]  Qs[dd][i]
    float* Ks = sm + 4096;     // [64][64]  Ks[dd][j]
    float* Ps = sm + 8192;     // [64][64]  Ps[i][j]
    float* Vs = sm + 12288;    // [64][65]  Vs[j][dd] (padded)

    int bh = blockIdx.y;
    int bb = bh >> 3, hh = bh & 7;
    int i0 = blockIdx.x * 64;
    const float* qp = qkv + ((size_t)bb*3*CH + hh*HD) * HW_;
    const float* kp = qp + (size_t)CH * HW_;
    const float* vp = qp + (size_t)2*CH * HW_;

    int tid = threadIdx.x;
    int tx = tid & 15, ty = tid >> 4;

    #pragma unroll
    for (int e = 0; e < 16; e++) {
        int idx = e*256 + tid;
        int dd = idx >> 6, ii = idx & 63;
        Qs[dd*64 + ii] = qp[(size_t)dd*HW_ + i0 + ii];
    }

    float m[4], l[4], o[4][4];
    #pragma unroll
    for (int r = 0; r < 4; r++) {
        m[r] = -1e30f; l[r] = 0.f;
        #pragma unroll
        for (int c2 = 0; c2 < 4; c2++) o[r][c2] = 0.f;
    }

    for (int j0 = 0; j0 < HW_; j0 += 64) {
        __syncthreads();   // protect Ks/Vs from previous-iteration readers
        #pragma unroll
        for (int e = 0; e < 16; e++) {
            int idx = e*256 + tid;
            int dd = idx >> 6, jj = idx & 63;
            Ks[dd*64 + jj] = kp[(size_t)dd*HW_ + j0 + jj];
            Vs[jj*65 + dd] = vp[(size_t)dd*HW_ + j0 + jj];
        }
        __syncthreads();

        // S = scale * Q K^T (4x4 microtile per thread)
        float s[4][4];
        #pragma unroll
        for (int r = 0; r < 4; r++)
            #pragma unroll
            for (int c2 = 0; c2 < 4; c2++) s[r][c2] = 0.f;

        #pragma unroll 8
        for (int dd = 0; dd < 64; dd++) {
            float4 a4 = *(const float4*)&Qs[dd*64 + ty*4];
            float4 b4 = *(const float4*)&Ks[dd*64 + tx*4];
            float av[4] = {a4.x, a4.y, a4.z, a4.w};
            float bw[4] = {b4.x, b4.y, b4.z, b4.w};
            #pragma unroll
            for (int r = 0; r < 4; r++)
                #pragma unroll
                for (int c2 = 0; c2 < 4; c2++)
                    s[r][c2] += av[r] * bw[c2];
        }

        // online softmax update; row stats reduced over the 16 tx-lanes
        #pragma unroll
        for (int r = 0; r < 4; r++) {
            float rmax = -1e30f;
            #pragma unroll
            for (int c2 = 0; c2 < 4; c2++) {
                s[r][c2] *= SCALE_;
                rmax = fmaxf(rmax, s[r][c2]);
            }
            #pragma unroll
            for (int off = 1; off < 16; off <<= 1)
                rmax = fmaxf(rmax, __shfl_xor_sync(0xffffffffu, rmax, off));
            float mn   = fmaxf(m[r], rmax);
            float corr = __expf(m[r] - mn);
            float p[4];
            float rsum = 0.f;
            #pragma unroll
            for (int c2 = 0; c2 < 4; c2++) {
                p[c2] = __expf(s[r][c2] - mn);
                rsum += p[c2];
            }
            #pragma unroll
            for (int off = 1; off < 16; off <<= 1)
                rsum += __shfl_xor_sync(0xffffffffu, rsum, off);
            l[r] = l[r]*corr + rsum;
            m[r] = mn;
            #pragma unroll
            for (int c2 = 0; c2 < 4; c2++) o[r][c2] *= corr;
            float4 pv = make_float4(p[0], p[1], p[2], p[3]);
            *(float4*)&Ps[(ty*4 + r)*64 + tx*4] = pv;
        }
        __syncthreads();

        // O += P @ V
        #pragma unroll 4
        for (int j = 0; j < 64; j++) {
            float bw[4];
            #pragma unroll
            for (int c2 = 0; c2 < 4; c2++) bw[c2] = Vs[j*65 + tx*4 + c2];
            #pragma unroll
            for (int r = 0; r < 4; r++) {
                float a = Ps[(ty*4 + r)*64 + j];
                #pragma unroll
                for (int c2 = 0; c2 < 4; c2++) o[r][c2] += a * bw[c2];
            }
        }
    }

    __syncthreads();
    // normalize; stage into Vs[i][dd] (pad 65 -> conflict-free transpose read)
    #pragma unroll
    for (int r = 0; r < 4; r++) {
        float invl = 1.f / l[r];
        #pragma unroll
        for (int c2 = 0; c2 < 4; c2++)
            Vs[(ty*4 + r)*65 + tx*4 + c2] = o[r][c2] * invl;
    }
    __syncthreads();

    float* ob = outp + ((size_t)bb*CH + hh*HD) * HW_;
    #pragma unroll
    for (int e = 0; e < 16; e++) {
        int idx = e*256 + tid;
        int dd = idx >> 6, ii = idx & 63;
        ob[(size_t)dd*HW_ + i0 + ii] = Vs[ii*65 + dd];
    }
}

// ---------------------------------------------------------------------------
extern "C" void kernel_launch(void* const* d_in, const int* in_sizes, int n_in,
                              void* d_out, int out_size)
{
    const float* x      = (const float*)d_in[0];
    const float* gn_w   = (const float*)d_in[1];
    const float* gn_b   = (const float*)d_in[2];
    const float* qkv_w  = (const float*)d_in[3];
    const float* qkv_b  = (const float*)d_in[4];
    const float* proj_w = (const float*)d_in[5];
    const float* proj_b = (const float*)d_in[6];
    float* out = (float*)d_out;

    float *xn, *qkvb, *att;
    cudaGetSymbolAddress((void**)&xn,   g_xn);
    cudaGetSymbolAddress((void**)&qkvb, g_qkv);
    cudaGetSymbolAddress((void**)&att,  g_att);

    const int ATT_SMEM = (4096*3 + 64*65) * sizeof(float);  // 65792 B
    cudaFuncSetAttribute(attention_kernel,
                         cudaFuncAttributeMaxDynamicSharedMemorySize, ATT_SMEM);

    // 1) GroupNorm
    groupnorm_kernel<<<BATCH*NGROUPS, 256>>>(x, gn_w, gn_b, xn);

    // 2) qkv 1x1 conv: [1536x512] x [512x1024] per batch
    sgemm_kernel<<<dim3(HW_/128, (3*CH)/128, BATCH), 256>>>(
        qkv_w, xn, qkvb, qkv_b, (const float*)0, 3*CH, CH, HW_);

    // 3) fused attention
    attention_kernel<<<dim3(HW_/64, BATCH*NH), 256, ATT_SMEM>>>(qkvb, att);

    // 4) proj + bias + residual
    sgemm_kernel<<<dim3(HW_/128, CH/128, BATCH), 256>>>(
        proj_w, att, out, proj_b, x, CH, CH, HW_);
}

// round 3
// speedup vs baseline: 2.2085x; 2.2085x over previous
#include <cuda_runtime.h>
#include <math.h>
#include <stdint.h>

#define BATCH   16
#define CH      512
#define HW_     1024
#define NGROUPS 8
#define CG      (CH/NGROUPS)
#define NH      8
#define HD      64
#define EPS_    1e-5f
#define SCALE_  0.125f

// Scratch (allocation-free)
__device__ float g_xn [BATCH*CH*HW_];
__device__ float g_qkv[(size_t)BATCH*3*CH*HW_];
__device__ float g_att[BATCH*CH*HW_];

__device__ __forceinline__ uint32_t f2tf32(float f) {
    uint32_t u;
    asm("cvt.rna.tf32.f32 %0, %1;" : "=r"(u) : "f"(f));
    return u;
}

__device__ __forceinline__ void mma_tf32(float* c, const uint32_t* a, const uint32_t* b) {
    asm volatile("mma.sync.aligned.m16n8k8.row.col.f32.tf32.tf32.f32 "
        "{%0,%1,%2,%3},{%4,%5,%6,%7},{%8,%9},{%0,%1,%2,%3};"
        : "+f"(c[0]), "+f"(c[1]), "+f"(c[2]), "+f"(c[3])
        : "r"(a[0]), "r"(a[1]), "r"(a[2]), "r"(a[3]), "r"(b[0]), "r"(b[1]));
}

// ---------------------------------------------------------------------------
// GroupNorm (unchanged: ~40us, bandwidth-trivial)
// ---------------------------------------------------------------------------
__global__ void groupnorm_kernel(const float* __restrict__ x,
                                 const float* __restrict__ w,
                                 const float* __restrict__ bias,
                                 float* __restrict__ xn)
{
    int bg = blockIdx.x;
    int bb = bg / NGROUPS, g = bg % NGROUPS;
    const float* xp = x  + ((size_t)bb*CH + g*CG) * HW_;
    float*       op = xn + ((size_t)bb*CH + g*CG) * HW_;
    const int NEL = CG * HW_;
    int tid = threadIdx.x;

    float s = 0.f, ss = 0.f;
    for (int i = tid*4; i < NEL; i += blockDim.x*4) {
        float4 v = *(const float4*)&xp[i];
        s  += v.x + v.y + v.z + v.w;
        ss += v.x*v.x + v.y*v.y + v.z*v.z + v.w*v.w;
    }
    __shared__ float r1[256], r2[256];
    r1[tid] = s; r2[tid] = ss;
    __syncthreads();
    for (int st = 128; st > 0; st >>= 1) {
        if (tid < st) { r1[tid] += r1[tid+st]; r2[tid] += r2[tid+st]; }
        __syncthreads();
    }
    float mean = r1[0] * (1.f/NEL);
    float var  = r2[0] * (1.f/NEL) - mean*mean;
    float inv  = rsqrtf(var + EPS_);

    for (int i = tid*4; i < NEL; i += blockDim.x*4) {
        int ch = g*CG + (i >> 10);
        float wc = w[ch], bc = bias[ch];
        float4 v = *(const float4*)&xp[i];
        float4 o;
        o.x = (v.x - mean)*inv*wc + bc;
        o.y = (v.y - mean)*inv*wc + bc;
        o.z = (v.z - mean)*inv*wc + bc;
        o.w = (v.w - mean)*inv*wc + bc;
        *(float4*)&op[i] = o;
    }
}

// ---------------------------------------------------------------------------
// tf32 MMA GEMM: C[bz] = A[MxK] * B[bz][KxN] + bias (+residual)
// 128x128x32 tile, 256 threads = 8 warps (2M x 4N), each warp 64x32.
// Smem: As[m][k] stride 36 (conflict-free A frags), Bs[k][n] stride 136.
// ---------------------------------------------------------------------------
#define GBM 128
#define GBN 128
#define GBK 32

__global__ __launch_bounds__(256)
void mma_gemm_kernel(const float* __restrict__ A,
                     const float* __restrict__ Bbase,
                     float* __restrict__ Cbase,
                     const float* __restrict__ bias,
                     const float* __restrict__ Rbase,
                     int M, int K, int N)
{
    __shared__ uint32_t As[GBM*36];
    __shared__ uint32_t Bs[GBK*136];

    int bz = blockIdx.z;
    const float* Bm = Bbase + (size_t)bz * K * N;
    float*       Cm = Cbase + (size_t)bz * M * N;
    const float* Rm = Rbase ? (Rbase + (size_t)bz * M * N) : (const float*)0;

    int m0 = blockIdx.y * GBM, n0 = blockIdx.x * GBN;
    int tid = threadIdx.x, lane = tid & 31, warp = tid >> 5;
    int wm = (warp >> 2) * 64, wn = (warp & 3) * 32;

    int arow = tid >> 3, acol = (tid & 7) * 4;   // A loader: rows arow+r*32, cols acol..+3
    int brow = tid >> 5, bcol = (tid & 31) * 4;  // B loader: rows brow+r*8, cols bcol..+3

    float c[4][4][4];
    #pragma unroll
    for (int mt = 0; mt < 4; mt++)
        #pragma unroll
        for (int nt = 0; nt < 4; nt++)
            #pragma unroll
            for (int e = 0; e < 4; e++) c[mt][nt][e] = 0.f;

    float4 areg[4], breg[4];
    #pragma unroll
    for (int r = 0; r < 4; r++) {
        areg[r] = *(const float4*)&A[(size_t)(m0 + arow + r*32)*K + acol];
        breg[r] = *(const float4*)&Bm[(size_t)(brow + r*8)*N + n0 + bcol];
    }

    for (int k0 = 0; k0 < K; k0 += GBK) {
        // store staged tile (convert to tf32)
        #pragma unroll
        for (int r = 0; r < 4; r++) {
            uint4 ua, ub;
            ua.x = f2tf32(areg[r].x); ua.y = f2tf32(areg[r].y);
            ua.z = f2tf32(areg[r].z); ua.w = f2tf32(areg[r].w);
            *(uint4*)&As[(arow + r*32)*36 + acol] = ua;
            ub.x = f2tf32(breg[r].x); ub.y = f2tf32(breg[r].y);
            ub.z = f2tf32(breg[r].z); ub.w = f2tf32(breg[r].w);
            *(uint4*)&Bs[(brow + r*8)*136 + bcol] = ub;
        }
        __syncthreads();

        if (k0 + GBK < K) {
            #pragma unroll
            for (int r = 0; r < 4; r++) {
                areg[r] = *(const float4*)&A[(size_t)(m0 + arow + r*32)*K + k0 + GBK + acol];
                breg[r] = *(const float4*)&Bm[(size_t)(brow + r*8)*N + k0 + GBK == 0 ? 0 : (size_t)(k0 + GBK + brow + r*8)*N + n0 + bcol];
            }
        }
        // NOTE: the B prefetch line above must index rows (k0+GBK+brow+r*8); rewrite cleanly:
        if (k0 + GBK < K) {
            #pragma unroll
            for (int r = 0; r < 4; r++) {
                areg[r] = *(const float4*)&A[(size_t)(m0 + arow + r*32)*K + (k0 + GBK) + acol];
                breg[r] = *(const float4*)&Bm[(size_t)((k0 + GBK) + brow + r*8)*N + n0 + bcol];
            }
        }

        #pragma unroll
        for (int ks = 0; ks < 4; ks++) {
            uint32_t a[4][4], b[4][2];
            #pragma unroll
            for (int mt = 0; mt < 4; mt++) {
                int row = wm + mt*16 + (lane >> 2);
                int col = ks*8 + (lane & 3);
                a[mt][0] = As[row*36 + col];
                a[mt][1] = As[(row+8)*36 + col];
                a[mt][2] = As[row*36 + col + 4];
                a[mt][3] = As[(row+8)*36 + col + 4];
            }
            #pragma unroll
            for (int nt = 0; nt < 4; nt++) {
                int kk = ks*8 + (lane & 3);
                int nn = wn + nt*8 + (lane >> 2);
                b[nt][0] = Bs[kk*136 + nn];
                b[nt][1] = Bs[(kk+4)*136 + nn];
            }
            #pragma unroll
            for (int mt = 0; mt < 4; mt++)
                #pragma unroll
                for (int nt = 0; nt < 4; nt++)
                    mma_tf32(c[mt][nt], a[mt], b[nt]);
        }
        __syncthreads();
    }

    // epilogue
    #pragma unroll
    for (int mt = 0; mt < 4; mt++) {
        #pragma unroll
        for (int half = 0; half < 2; half++) {
            int m = m0 + wm + mt*16 + (lane >> 2) + half*8;
            float bvv = bias ? bias[m] : 0.f;
            #pragma unroll
            for (int nt = 0; nt < 4; nt++) {
                int n = n0 + wn + nt*8 + 2*(lane & 3);
                float2 o;
                o.x = c[mt][nt][half*2 + 0] + bvv;
                o.y = c[mt][nt][half*2 + 1] + bvv;
                if (Rm) {
                    float2 r = *(const float2*)&Rm[(size_t)m*N + n];
                    o.x += r.x; o.y += r.y;
                }
                *(float2*)&Cm[(size_t)m*N + n] = o;
            }
        }
    }
}

// ---------------------------------------------------------------------------
// Flash attention with tf32 MMA. Block = 64 queries of one (b,h).
// 128 threads = 4 warps, warp owns 16 query rows. Q frags register-resident.
// Smem: Qs/Ps [64][68] (dual use), Ks [64][68], Vs [64][72]. 53248 B dynamic.
// ---------------------------------------------------------------------------
__global__ __launch_bounds__(128)
void attention_kernel(const float* __restrict__ qkv,
                      float* __restrict__ outp)
{
    extern __shared__ uint32_t smd[];
    uint32_t* Ps = smd;                 // [64][68] — Q staging, then P, then O out
    uint32_t* Ks = smd + 64*68;         // [64][68]  Ks[j][d]
    uint32_t* Vs = smd + 2*64*68;       // [64][72]  Vs[j][d]

    int bh = blockIdx.y;
    int bb = bh >> 3, hh = bh & 7;
    int i0 = blockIdx.x * 64;
    const float* qp = qkv + ((size_t)bb*3*CH + hh*HD) * HW_;
    const float* kp = qp + (size_t)CH * HW_;
    const float* vp = qp + (size_t)2*CH * HW_;

    int tid = threadIdx.x, lane = tid & 31, warp = tid >> 5;

    // stage Q (transpose to [i][d], tf32)
    #pragma unroll
    for (int e = 0; e < 32; e++) {
        int idx = e*128 + tid;
        int d = idx >> 6, i = idx & 63;
        Ps[i*68 + d] = f2tf32(qp[(size_t)d*HW_ + i0 + i]);
    }
    __syncthreads();

    // Q fragments, register resident: row block = warp*16
    uint32_t qf[8][4];
    {
        int row = warp*16 + (lane >> 2);
        #pragma unroll
        for (int ks = 0; ks < 8; ks++) {
            int col = ks*8 + (lane & 3);
            qf[ks][0] = Ps[row*68 + col];
            qf[ks][1] = Ps[(row+8)*68 + col];
            qf[ks][2] = Ps[row*68 + col + 4];
            qf[ks][3] = Ps[(row+8)*68 + col + 4];
        }
    }
    __syncthreads();

    float m0v = -1e30f, m1v = -1e30f, l0 = 0.f, l1 = 0.f;
    float o[8][4];
    #pragma unroll
    for (int dt = 0; dt < 8; dt++)
        #pragma unroll
        for (int e = 0; e < 4; e++) o[dt][e] = 0.f;

    for (int j0 = 0; j0 < HW_; j0 += 64) {
        __syncthreads();
        // load K, V tiles (transpose to [j][d], tf32)
        #pragma unroll
        for (int e = 0; e < 32; e++) {
            int idx = e*128 + tid;
            int d = idx >> 6, j = idx & 63;
            Ks[j*68 + d] = f2tf32(kp[(size_t)d*HW_ + j0 + j]);
            Vs[j*72 + d] = f2tf32(vp[(size_t)d*HW_ + j0 + j]);
        }
        __syncthreads();

        // S = Q K^T
        float s[8][4];
        #pragma unroll
        for (int nt = 0; nt < 8; nt++)
            #pragma unroll
            for (int e = 0; e < 4; e++) s[nt][e] = 0.f;

        #pragma unroll
        for (int ks = 0; ks < 8; ks++) {
            int kk = ks*8 + (lane & 3);
            #pragma unroll
            for (int nt = 0; nt < 8; nt++) {
                uint32_t b[2];
                int jj = nt*8 + (lane >> 2);
                b[0] = Ks[jj*68 + kk];
                b[1] = Ks[jj*68 + kk + 4];
                mma_tf32(s[nt], qf[ks], b);
            }
        }

        // online softmax: thread rows r0 = warp*16+lane/4, r1 = r0+8
        float rmax0 = -1e30f, rmax1 = -1e30f;
        #pragma unroll
        for (int nt = 0; nt < 8; nt++) {
            s[nt][0] *= SCALE_; s[nt][1] *= SCALE_;
            s[nt][2] *= SCALE_; s[nt][3] *= SCALE_;
            rmax0 = fmaxf(rmax0, fmaxf(s[nt][0], s[nt][1]));
            rmax1 = fmaxf(rmax1, fmaxf(s[nt][2], s[nt][3]));
        }
        #pragma unroll
        for (int off = 1; off < 4; off <<= 1) {
            rmax0 = fmaxf(rmax0, __shfl_xor_sync(0xffffffffu, rmax0, off));
            rmax1 = fmaxf(rmax1, __shfl_xor_sync(0xffffffffu, rmax1, off));
        }
        float mn0 = fmaxf(m0v, rmax0), mn1 = fmaxf(m1v, rmax1);
        float corr0 = __expf(m0v - mn0), corr1 = __expf(m1v - mn1);
        m0v = mn0; m1v = mn1;

        float rs0 = 0.f, rs1 = 0.f;
        #pragma unroll
        for (int nt = 0; nt < 8; nt++) {
            s[nt][0] = __expf(s[nt][0] - mn0);
            s[nt][1] = __expf(s[nt][1] - mn0);
            s[nt][2] = __expf(s[nt][2] - mn1);
            s[nt][3] = __expf(s[nt][3] - mn1);
            rs0 += s[nt][0] + s[nt][1];
            rs1 += s[nt][2] + s[nt][3];
        }
        #pragma unroll
        for (int off = 1; off < 4; off <<= 1) {
            rs0 += __shfl_xor_sync(0xffffffffu, rs0, off);
            rs1 += __shfl_xor_sync(0xffffffffu, rs1, off);
        }
        l0 = l0*corr0 + rs0;
        l1 = l1*corr1 + rs1;
        #pragma unroll
        for (int dt = 0; dt < 8; dt++) {
            o[dt][0] *= corr0; o[dt][1] *= corr0;
            o[dt][2] *= corr1; o[dt][3] *= corr1;
        }

        // write P (tf32) to smem for A-frag reload
        {
            int r0 = warp*16 + (lane >> 2);
            #pragma unroll
            for (int nt = 0; nt < 8; nt++) {
                int col = nt*8 + 2*(lane & 3);
                uint2 p0, p1;
                p0.x = f2tf32(s[nt][0]); p0.y = f2tf32(s[nt][1]);
                p1.x = f2tf32(s[nt][2]); p1.y = f2tf32(s[nt][3]);
                *(uint2*)&Ps[r0*68 + col]     = p0;
                *(uint2*)&Ps[(r0+8)*68 + col] = p1;
            }
        }
        __syncthreads();

        // O += P @ V
        #pragma unroll
        for (int ks = 0; ks < 8; ks++) {
            uint32_t pa[4];
            int row = warp*16 + (lane >> 2);
            int col = ks*8 + (lane & 3);
            pa[0] = Ps[row*68 + col];
            pa[1] = Ps[(row+8)*68 + col];
            pa[2] = Ps[row*68 + col + 4];
            pa[3] = Ps[(row+8)*68 + col + 4];
            int jj = ks*8 + (lane & 3);
            #pragma unroll
            for (int dt = 0; dt < 8; dt++) {
                uint32_t b[2];
                int dd = dt*8 + (lane >> 2);
                b[0] = Vs[jj*72 + dd];
                b[1] = Vs[(jj+4)*72 + dd];
                mma_tf32(o[dt], pa, b);
            }
        }
    }

    __syncthreads();
    // normalize, stage O (fp32) into Ps buffer as [i][d]
    {
        float* PsF = (float*)Ps;
        float inv0 = 1.f / l0, inv1 = 1.f / l1;
        int r0 = warp*16 + (lane >> 2);
        #pragma unroll
        for (int dt = 0; dt < 8; dt++) {
            int col = dt*8 + 2*(lane & 3);
            float2 v0, v1;
            v0.x = o[dt][0]*inv0; v0.y = o[dt][1]*inv0;
            v1.x = o[dt][2]*inv1; v1.y = o[dt][3]*inv1;
            *(float2*)&PsF[r0*68 + col]     = v0;
            *(float2*)&PsF[(r0+8)*68 + col] = v1;
        }
    }
    __syncthreads();

    // coalesced store out[d][i]
    float* ob = outp + ((size_t)bb*CH + hh*HD) * HW_;
    const float* PsF = (const float*)Ps;
    #pragma unroll
    for (int e = 0; e < 32; e++) {
        int idx = e*128 + tid;
        int d = idx >> 6, i = idx & 63;
        ob[(size_t)d*HW_ + i0 + i] = PsF[i*68 + d];
    }
}

// ---------------------------------------------------------------------------
extern "C" void kernel_launch(void* const* d_in, const int* in_sizes, int n_in,
                              void* d_out, int out_size)
{
    const float* x      = (const float*)d_in[0];
    const float* gn_w   = (const float*)d_in[1];
    const float* gn_b   = (const float*)d_in[2];
    const float* qkv_w  = (const float*)d_in[3];
    const float* qkv_b  = (const float*)d_in[4];
    const float* proj_w = (const float*)d_in[5];
    const float* proj_b = (const float*)d_in[6];
    float* out = (float*)d_out;

    float *xn, *qkvb, *att;
    cudaGetSymbolAddress((void**)&xn,   g_xn);
    cudaGetSymbolAddress((void**)&qkvb, g_qkv);
    cudaGetSymbolAddress((void**)&att,  g_att);

    const int ATT_SMEM = (64*68*2 + 64*72) * 4;  // 53248 B
    cudaFuncSetAttribute(attention_kernel,
                         cudaFuncAttributeMaxDynamicSharedMemorySize, ATT_SMEM);

    groupnorm_kernel<<<BATCH*NGROUPS, 256>>>(x, gn_w, gn_b, xn);

    mma_gemm_kernel<<<dim3(HW_/GBN, (3*CH)/GBM, BATCH), 256>>>(
        qkv_w, xn, qkvb, qkv_b, (const float*)0, 3*CH, CH, HW_);

    attention_kernel<<<dim3(HW_/64, BATCH*NH), 128, ATT_SMEM>>>(qkvb, att);

    mma_gemm_kernel<<<dim3(HW_/GBN, CH/GBM, BATCH), 256>>>(
        proj_w, att, out, proj_b, x, CH, CH, HW_);
}

// round 4
// speedup vs baseline: 2.2179x; 1.0043x over previous
#include <cuda_runtime.h>
#include <math.h>
#include <stdint.h>

#define BATCH   16
#define CH      512
#define HW_     1024
#define NGROUPS 8
#define CG      (CH/NGROUPS)
#define NH      8
#define HD      64
#define EPS_    1e-5f
#define SCALE_  0.125f

// Scratch (allocation-free)
__device__ float g_xn [BATCH*CH*HW_];
__device__ float g_qkv[(size_t)BATCH*3*CH*HW_];
__device__ float g_att[BATCH*CH*HW_];

__device__ __forceinline__ uint32_t f2tf32(float f) {
    uint32_t u;
    asm("cvt.rna.tf32.f32 %0, %1;" : "=r"(u) : "f"(f));
    return u;
}

__device__ __forceinline__ void mma_tf32(float* c, const uint32_t* a, const uint32_t* b) {
    asm volatile("mma.sync.aligned.m16n8k8.row.col.f32.tf32.tf32.f32 "
        "{%0,%1,%2,%3},{%4,%5,%6,%7},{%8,%9},{%0,%1,%2,%3};"
        : "+f"(c[0]), "+f"(c[1]), "+f"(c[2]), "+f"(c[3])
        : "r"(a[0]), "r"(a[1]), "r"(a[2]), "r"(a[3]), "r"(b[0]), "r"(b[1]));
}

// ---------------------------------------------------------------------------
// GroupNorm (unchanged: ~40us, bandwidth-trivial)
// ---------------------------------------------------------------------------
__global__ void groupnorm_kernel(const float* __restrict__ x,
                                 const float* __restrict__ w,
                                 const float* __restrict__ bias,
                                 float* __restrict__ xn)
{
    int bg = blockIdx.x;
    int bb = bg / NGROUPS, g = bg % NGROUPS;
    const float* xp = x  + ((size_t)bb*CH + g*CG) * HW_;
    float*       op = xn + ((size_t)bb*CH + g*CG) * HW_;
    const int NEL = CG * HW_;
    int tid = threadIdx.x;

    float s = 0.f, ss = 0.f;
    for (int i = tid*4; i < NEL; i += blockDim.x*4) {
        float4 v = *(const float4*)&xp[i];
        s  += v.x + v.y + v.z + v.w;
        ss += v.x*v.x + v.y*v.y + v.z*v.z + v.w*v.w;
    }
    __shared__ float r1[256], r2[256];
    r1[tid] = s; r2[tid] = ss;
    __syncthreads();
    for (int st = 128; st > 0; st >>= 1) {
        if (tid < st) { r1[tid] += r1[tid+st]; r2[tid] += r2[tid+st]; }
        __syncthreads();
    }
    float mean = r1[0] * (1.f/NEL);
    float var  = r2[0] * (1.f/NEL) - mean*mean;
    float inv  = rsqrtf(var + EPS_);

    for (int i = tid*4; i < NEL; i += blockDim.x*4) {
        int ch = g*CG + (i >> 10);
        float wc = w[ch], bc = bias[ch];
        float4 v = *(const float4*)&xp[i];
        float4 o;
        o.x = (v.x - mean)*inv*wc + bc;
        o.y = (v.y - mean)*inv*wc + bc;
        o.z = (v.z - mean)*inv*wc + bc;
        o.w = (v.w - mean)*inv*wc + bc;
        *(float4*)&op[i] = o;
    }
}

// ---------------------------------------------------------------------------
// tf32 MMA GEMM: C[bz] = A[MxK] * B[bz][KxN] + bias (+residual)
// 128x128x32 tile, 256 threads = 8 warps (2M x 4N), each warp 64x32.
// Smem: As[m][k] stride 36 (conflict-free A frags), Bs[k][n] stride 136.
// ---------------------------------------------------------------------------
#define GBM 128
#define GBN 128
#define GBK 32

__global__ __launch_bounds__(256)
void mma_gemm_kernel(const float* __restrict__ A,
                     const float* __restrict__ Bbase,
                     float* __restrict__ Cbase,
                     const float* __restrict__ bias,
                     const float* __restrict__ Rbase,
                     int M, int K, int N)
{
    __shared__ uint32_t As[GBM*36];
    __shared__ uint32_t Bs[GBK*136];

    int bz = blockIdx.z;
    const float* Bm = Bbase + (size_t)bz * K * N;
    float*       Cm = Cbase + (size_t)bz * M * N;
    const float* Rm = Rbase ? (Rbase + (size_t)bz * M * N) : (const float*)0;

    int m0 = blockIdx.y * GBM, n0 = blockIdx.x * GBN;
    int tid = threadIdx.x, lane = tid & 31, warp = tid >> 5;
    int wm = (warp >> 2) * 64, wn = (warp & 3) * 32;

    int arow = tid >> 3, acol = (tid & 7) * 4;   // A loader: rows arow+r*32, cols acol..+3
    int brow = tid >> 5, bcol = (tid & 31) * 4;  // B loader: rows brow+r*8, cols bcol..+3

    float c[4][4][4];
    #pragma unroll
    for (int mt = 0; mt < 4; mt++)
        #pragma unroll
        for (int nt = 0; nt < 4; nt++)
            #pragma unroll
            for (int e = 0; e < 4; e++) c[mt][nt][e] = 0.f;

    float4 areg[4], breg[4];
    #pragma unroll
    for (int r = 0; r < 4; r++) {
        areg[r] = *(const float4*)&A[(size_t)(m0 + arow + r*32)*K + acol];
        breg[r] = *(const float4*)&Bm[(size_t)(brow + r*8)*N + n0 + bcol];
    }

    for (int k0 = 0; k0 < K; k0 += GBK) {
        // store staged tile (convert to tf32)
        #pragma unroll
        for (int r = 0; r < 4; r++) {
            uint4 ua, ub;
            ua.x = f2tf32(areg[r].x); ua.y = f2tf32(areg[r].y);
            ua.z = f2tf32(areg[r].z); ua.w = f2tf32(areg[r].w);
            *(uint4*)&As[(arow + r*32)*36 + acol] = ua;
            ub.x = f2tf32(breg[r].x); ub.y = f2tf32(breg[r].y);
            ub.z = f2tf32(breg[r].z); ub.w = f2tf32(breg[r].w);
            *(uint4*)&Bs[(brow + r*8)*136 + bcol] = ub;
        }
        __syncthreads();

        if (k0 + GBK < K) {
            #pragma unroll
            for (int r = 0; r < 4; r++) {
                areg[r] = *(const float4*)&A[(size_t)(m0 + arow + r*32)*K + k0 + GBK + acol];
                breg[r] = *(const float4*)&Bm[(size_t)(brow + r*8)*N + k0 + GBK == 0 ? 0 : (size_t)(k0 + GBK + brow + r*8)*N + n0 + bcol];
            }
        }
        // NOTE: the B prefetch line above must index rows (k0+GBK+brow+r*8); rewrite cleanly:
        if (k0 + GBK < K) {
            #pragma unroll
            for (int r = 0; r < 4; r++) {
                areg[r] = *(const float4*)&A[(size_t)(m0 + arow + r*32)*K + (k0 + GBK) + acol];
                breg[r] = *(const float4*)&Bm[(size_t)((k0 + GBK) + brow + r*8)*N + n0 + bcol];
            }
        }

        #pragma unroll
        for (int ks = 0; ks < 4; ks++) {
            uint32_t a[4][4], b[4][2];
            #pragma unroll
            for (int mt = 0; mt < 4; mt++) {
                int row = wm + mt*16 + (lane >> 2);
                int col = ks*8 + (lane & 3);
                a[mt][0] = As[row*36 + col];
                a[mt][1] = As[(row+8)*36 + col];
                a[mt][2] = As[row*36 + col + 4];
                a[mt][3] = As[(row+8)*36 + col + 4];
            }
            #pragma unroll
            for (int nt = 0; nt < 4; nt++) {
                int kk = ks*8 + (lane & 3);
                int nn = wn + nt*8 + (lane >> 2);
                b[nt][0] = Bs[kk*136 + nn];
                b[nt][1] = Bs[(kk+4)*136 + nn];
            }
            #pragma unroll
            for (int mt = 0; mt < 4; mt++)
                #pragma unroll
                for (int nt = 0; nt < 4; nt++)
                    mma_tf32(c[mt][nt], a[mt], b[nt]);
        }
        __syncthreads();
    }

    // epilogue
    #pragma unroll
    for (int mt = 0; mt < 4; mt++) {
        #pragma unroll
        for (int half = 0; half < 2; half++) {
            int m = m0 + wm + mt*16 + (lane >> 2) + half*8;
            float bvv = bias ? bias[m] : 0.f;
            #pragma unroll
            for (int nt = 0; nt < 4; nt++) {
                int n = n0 + wn + nt*8 + 2*(lane & 3);
                float2 o;
                o.x = c[mt][nt][half*2 + 0] + bvv;
                o.y = c[mt][nt][half*2 + 1] + bvv;
                if (Rm) {
                    float2 r = *(const float2*)&Rm[(size_t)m*N + n];
                    o.x += r.x; o.y += r.y;
                }
                *(float2*)&Cm[(size_t)m*N + n] = o;
            }
        }
    }
}

// ---------------------------------------------------------------------------
// Flash attention with tf32 MMA. Block = 64 queries of one (b,h).
// 128 threads = 4 warps, warp owns 16 query rows. Q frags register-resident.
// Smem: Qs/Ps [64][68] (dual use), Ks [64][68], Vs [64][72]. 53248 B dynamic.
// ---------------------------------------------------------------------------
__global__ __launch_bounds__(128)
void attention_kernel(const float* __restrict__ qkv,
                      float* __restrict__ outp)
{
    extern __shared__ uint32_t smd[];
    uint32_t* Ps = smd;                 // [64][68] — Q staging, then P, then O out
    uint32_t* Ks = smd + 64*68;         // [64][68]  Ks[j][d]
    uint32_t* Vs = smd + 2*64*68;       // [64][72]  Vs[j][d]

    int bh = blockIdx.y;
    int bb = bh >> 3, hh = bh & 7;
    int i0 = blockIdx.x * 64;
    const float* qp = qkv + ((size_t)bb*3*CH + hh*HD) * HW_;
    const float* kp = qp + (size_t)CH * HW_;
    const float* vp = qp + (size_t)2*CH * HW_;

    int tid = threadIdx.x, lane = tid & 31, warp = tid >> 5;

    // stage Q (transpose to [i][d], tf32)
    #pragma unroll
    for (int e = 0; e < 32; e++) {
        int idx = e*128 + tid;
        int d = idx >> 6, i = idx & 63;
        Ps[i*68 + d] = f2tf32(qp[(size_t)d*HW_ + i0 + i]);
    }
    __syncthreads();

    // Q fragments, register resident: row block = warp*16
    uint32_t qf[8][4];
    {
        int row = warp*16 + (lane >> 2);
        #pragma unroll
        for (int ks = 0; ks < 8; ks++) {
            int col = ks*8 + (lane & 3);
            qf[ks][0] = Ps[row*68 + col];
            qf[ks][1] = Ps[(row+8)*68 + col];
            qf[ks][2] = Ps[row*68 + col + 4];
            qf[ks][3] = Ps[(row+8)*68 + col + 4];
        }
    }
    __syncthreads();

    float m0v = -1e30f, m1v = -1e30f, l0 = 0.f, l1 = 0.f;
    float o[8][4];
    #pragma unroll
    for (int dt = 0; dt < 8; dt++)
        #pragma unroll
        for (int e = 0; e < 4; e++) o[dt][e] = 0.f;

    for (int j0 = 0; j0 < HW_; j0 += 64) {
        __syncthreads();
        // load K, V tiles (transpose to [j][d], tf32)
        #pragma unroll
        for (int e = 0; e < 32; e++) {
            int idx = e*128 + tid;
            int d = idx >> 6, j = idx & 63;
            Ks[j*68 + d] = f2tf32(kp[(size_t)d*HW_ + j0 + j]);
            Vs[j*72 + d] = f2tf32(vp[(size_t)d*HW_ + j0 + j]);
        }
        __syncthreads();

        // S = Q K^T
        float s[8][4];
        #pragma unroll
        for (int nt = 0; nt < 8; nt++)
            #pragma unroll
            for (int e = 0; e < 4; e++) s[nt][e] = 0.f;

        #pragma unroll
        for (int ks = 0; ks < 8; ks++) {
            int kk = ks*8 + (lane & 3);
            #pragma unroll
            for (int nt = 0; nt < 8; nt++) {
                uint32_t b[2];
                int jj = nt*8 + (lane >> 2);
                b[0] = Ks[jj*68 + kk];
                b[1] = Ks[jj*68 + kk + 4];
                mma_tf32(s[nt], qf[ks], b);
            }
        }

        // online softmax: thread rows r0 = warp*16+lane/4, r1 = r0+8
        float rmax0 = -1e30f, rmax1 = -1e30f;
        #pragma unroll
        for (int nt = 0; nt < 8; nt++) {
            s[nt][0] *= SCALE_; s[nt][1] *= SCALE_;
            s[nt][2] *= SCALE_; s[nt][3] *= SCALE_;
            rmax0 = fmaxf(rmax0, fmaxf(s[nt][0], s[nt][1]));
            rmax1 = fmaxf(rmax1, fmaxf(s[nt][2], s[nt][3]));
        }
        #pragma unroll
        for (int off = 1; off < 4; off <<= 1) {
            rmax0 = fmaxf(rmax0, __shfl_xor_sync(0xffffffffu, rmax0, off));
            rmax1 = fmaxf(rmax1, __shfl_xor_sync(0xffffffffu, rmax1, off));
        }
        float mn0 = fmaxf(m0v, rmax0), mn1 = fmaxf(m1v, rmax1);
        float corr0 = __expf(m0v - mn0), corr1 = __expf(m1v - mn1);
        m0v = mn0; m1v = mn1;

        float rs0 = 0.f, rs1 = 0.f;
        #pragma unroll
        for (int nt = 0; nt < 8; nt++) {
            s[nt][0] = __expf(s[nt][0] - mn0);
            s[nt][1] = __expf(s[nt][1] - mn0);
            s[nt][2] = __expf(s[nt][2] - mn1);
            s[nt][3] = __expf(s[nt][3] - mn1);
            rs0 += s[nt][0] + s[nt][1];
            rs1 += s[nt][2] + s[nt][3];
        }
        #pragma unroll
        for (int off = 1; off < 4; off <<= 1) {
            rs0 += __shfl_xor_sync(0xffffffffu, rs0, off);
            rs1 += __shfl_xor_sync(0xffffffffu, rs1, off);
        }
        l0 = l0*corr0 + rs0;
        l1 = l1*corr1 + rs1;
        #pragma unroll
        for (int dt = 0; dt < 8; dt++) {
            o[dt][0] *= corr0; o[dt][1] *= corr0;
            o[dt][2] *= corr1; o[dt][3] *= corr1;
        }

        // write P (tf32) to smem for A-frag reload
        {
            int r0 = warp*16 + (lane >> 2);
            #pragma unroll
            for (int nt = 0; nt < 8; nt++) {
                int col = nt*8 + 2*(lane & 3);
                uint2 p0, p1;
                p0.x = f2tf32(s[nt][0]); p0.y = f2tf32(s[nt][1]);
                p1.x = f2tf32(s[nt][2]); p1.y = f2tf32(s[nt][3]);
                *(uint2*)&Ps[r0*68 + col]     = p0;
                *(uint2*)&Ps[(r0+8)*68 + col] = p1;
            }
        }
        __syncthreads();

        // O += P @ V
        #pragma unroll
        for (int ks = 0; ks < 8; ks++) {
            uint32_t pa[4];
            int row = warp*16 + (lane >> 2);
            int col = ks*8 + (lane & 3);
            pa[0] = Ps[row*68 + col];
            pa[1] = Ps[(row+8)*68 + col];
            pa[2] = Ps[row*68 + col + 4];
            pa[3] = Ps[(row+8)*68 + col + 4];
            int jj = ks*8 + (lane & 3);
            #pragma unroll
            for (int dt = 0; dt < 8; dt++) {
                uint32_t b[2];
                int dd = dt*8 + (lane >> 2);
                b[0] = Vs[jj*72 + dd];
                b[1] = Vs[(jj+4)*72 + dd];
                mma_tf32(o[dt], pa, b);
            }
        }
    }

    __syncthreads();
    // normalize, stage O (fp32) into Ps buffer as [i][d]
    {
        float* PsF = (float*)Ps;
        float inv0 = 1.f / l0, inv1 = 1.f / l1;
        int r0 = warp*16 + (lane >> 2);
        #pragma unroll
        for (int dt = 0; dt < 8; dt++) {
            int col = dt*8 + 2*(lane & 3);
            float2 v0, v1;
            v0.x = o[dt][0]*inv0; v0.y = o[dt][1]*inv0;
            v1.x = o[dt][2]*inv1; v1.y = o[dt][3]*inv1;
            *(float2*)&PsF[r0*68 + col]     = v0;
            *(float2*)&PsF[(r0+8)*68 + col] = v1;
        }
    }
    __syncthreads();

    // coalesced store out[d][i]
    float* ob = outp + ((size_t)bb*CH + hh*HD) * HW_;
    const float* PsF = (const float*)Ps;
    #pragma unroll
    for (int e = 0; e < 32; e++) {
        int idx = e*128 + tid;
        int d = idx >> 6, i = idx & 63;
        ob[(size_t)d*HW_ + i0 + i] = PsF[i*68 + d];
    }
}

// ---------------------------------------------------------------------------
extern "C" void kernel_launch(void* const* d_in, const int* in_sizes, int n_in,
                              void* d_out, int out_size)
{
    const float* x      = (const float*)d_in[0];
    const float* gn_w   = (const float*)d_in[1];
    const float* gn_b   = (const float*)d_in[2];
    const float* qkv_w  = (const float*)d_in[3];
    const float* qkv_b  = (const float*)d_in[4];
    const float* proj_w = (const float*)d_in[5];
    const float* proj_b = (const float*)d_in[6];
    float* out = (float*)d_out;

    float *xn, *qkvb, *att;
    cudaGetSymbolAddress((void**)&xn,   g_xn);
    cudaGetSymbolAddress((void**)&qkvb, g_qkv);
    cudaGetSymbolAddress((void**)&att,  g_att);

    const int ATT_SMEM = (64*68*2 + 64*72) * 4;  // 53248 B
    cudaFuncSetAttribute(attention_kernel,
                         cudaFuncAttributeMaxDynamicSharedMemorySize, ATT_SMEM);

    groupnorm_kernel<<<BATCH*NGROUPS, 256>>>(x, gn_w, gn_b, xn);

    mma_gemm_kernel<<<dim3(HW_/GBN, (3*CH)/GBM, BATCH), 256>>>(
        qkv_w, xn, qkvb, qkv_b, (const float*)0, 3*CH, CH, HW_);

    attention_kernel<<<dim3(HW_/64, BATCH*NH), 128, ATT_SMEM>>>(qkvb, att);

    mma_gemm_kernel<<<dim3(HW_/GBN, CH/GBM, BATCH), 256>>>(
        proj_w, att, out, proj_b, x, CH, CH, HW_);
}

// round 5
// speedup vs baseline: 2.2188x; 1.0004x over previous
#include <cuda_runtime.h>
#include <math.h>
#include <stdint.h>

#define BATCH   16
#define CH      512
#define HW_     1024
#define NGROUPS 8
#define CG      (CH/NGROUPS)
#define NH      8
#define HD      64
#define EPS_    1e-5f
#define SCALE_  0.125f

// Scratch (allocation-free)
__device__ float g_xn [BATCH*CH*HW_];
__device__ float g_qkv[(size_t)BATCH*3*CH*HW_];
__device__ float g_att[BATCH*CH*HW_];

__device__ __forceinline__ uint32_t f2tf32(float f) {
    uint32_t u;
    asm("cvt.rna.tf32.f32 %0, %1;" : "=r"(u) : "f"(f));
    return u;
}

__device__ __forceinline__ void mma_tf32(float* c, const uint32_t* a, const uint32_t* b) {
    asm volatile("mma.sync.aligned.m16n8k8.row.col.f32.tf32.tf32.f32 "
        "{%0,%1,%2,%3},{%4,%5,%6,%7},{%8,%9},{%0,%1,%2,%3};"
        : "+f"(c[0]), "+f"(c[1]), "+f"(c[2]), "+f"(c[3])
        : "r"(a[0]), "r"(a[1]), "r"(a[2]), "r"(a[3]), "r"(b[0]), "r"(b[1]));
}

// ---------------------------------------------------------------------------
// GroupNorm (unchanged: ~40us, bandwidth-trivial)
// ---------------------------------------------------------------------------
__global__ void groupnorm_kernel(const float* __restrict__ x,
                                 const float* __restrict__ w,
                                 const float* __restrict__ bias,
                                 float* __restrict__ xn)
{
    int bg = blockIdx.x;
    int bb = bg / NGROUPS, g = bg % NGROUPS;
    const float* xp = x  + ((size_t)bb*CH + g*CG) * HW_;
    float*       op = xn + ((size_t)bb*CH + g*CG) * HW_;
    const int NEL = CG * HW_;
    int tid = threadIdx.x;

    float s = 0.f, ss = 0.f;
    for (int i = tid*4; i < NEL; i += blockDim.x*4) {
        float4 v = *(const float4*)&xp[i];
        s  += v.x + v.y + v.z + v.w;
        ss += v.x*v.x + v.y*v.y + v.z*v.z + v.w*v.w;
    }
    __shared__ float r1[256], r2[256];
    r1[tid] = s; r2[tid] = ss;
    __syncthreads();
    for (int st = 128; st > 0; st >>= 1) {
        if (tid < st) { r1[tid] += r1[tid+st]; r2[tid] += r2[tid+st]; }
        __syncthreads();
    }
    float mean = r1[0] * (1.f/NEL);
    float var  = r2[0] * (1.f/NEL) - mean*mean;
    float inv  = rsqrtf(var + EPS_);

    for (int i = tid*4; i < NEL; i += blockDim.x*4) {
        int ch = g*CG + (i >> 10);
        float wc = w[ch], bc = bias[ch];
        float4 v = *(const float4*)&xp[i];
        float4 o;
        o.x = (v.x - mean)*inv*wc + bc;
        o.y = (v.y - mean)*inv*wc + bc;
        o.z = (v.z - mean)*inv*wc + bc;
        o.w = (v.w - mean)*inv*wc + bc;
        *(float4*)&op[i] = o;
    }
}

// ---------------------------------------------------------------------------
// tf32 MMA GEMM: C[bz] = A[MxK] * B[bz][KxN] + bias (+residual)
// 128x128x32 tile, 256 threads = 8 warps (2M x 4N), each warp 64x32.
// Smem: As[m][k] stride 36 (conflict-free A frags), Bs[k][n] stride 136.
// ---------------------------------------------------------------------------
#define GBM 128
#define GBN 128
#define GBK 32

__global__ __launch_bounds__(256)
void mma_gemm_kernel(const float* __restrict__ A,
                     const float* __restrict__ Bbase,
                     float* __restrict__ Cbase,
                     const float* __restrict__ bias,
                     const float* __restrict__ Rbase,
                     int M, int K, int N)
{
    __shared__ uint32_t As[GBM*36];
    __shared__ uint32_t Bs[GBK*136];

    int bz = blockIdx.z;
    const float* Bm = Bbase + (size_t)bz * K * N;
    float*       Cm = Cbase + (size_t)bz * M * N;
    const float* Rm = Rbase ? (Rbase + (size_t)bz * M * N) : (const float*)0;

    int m0 = blockIdx.y * GBM, n0 = blockIdx.x * GBN;
    int tid = threadIdx.x, lane = tid & 31, warp = tid >> 5;
    int wm = (warp >> 2) * 64, wn = (warp & 3) * 32;

    int arow = tid >> 3, acol = (tid & 7) * 4;   // A loader: rows arow+r*32, cols acol..+3
    int brow = tid >> 5, bcol = (tid & 31) * 4;  // B loader: rows brow+r*8, cols bcol..+3

    float c[4][4][4];
    #pragma unroll
    for (int mt = 0; mt < 4; mt++)
        #pragma unroll
        for (int nt = 0; nt < 4; nt++)
            #pragma unroll
            for (int e = 0; e < 4; e++) c[mt][nt][e] = 0.f;

    float4 areg[4], breg[4];
    #pragma unroll
    for (int r = 0; r < 4; r++) {
        areg[r] = *(const float4*)&A[(size_t)(m0 + arow + r*32)*K + acol];
        breg[r] = *(const float4*)&Bm[(size_t)(brow + r*8)*N + n0 + bcol];
    }

    for (int k0 = 0; k0 < K; k0 += GBK) {
        // store staged tile (convert to tf32)
        #pragma unroll
        for (int r = 0; r < 4; r++) {
            uint4 ua, ub;
            ua.x = f2tf32(areg[r].x); ua.y = f2tf32(areg[r].y);
            ua.z = f2tf32(areg[r].z); ua.w = f2tf32(areg[r].w);
            *(uint4*)&As[(arow + r*32)*36 + acol] = ua;
            ub.x = f2tf32(breg[r].x); ub.y = f2tf32(breg[r].y);
            ub.z = f2tf32(breg[r].z); ub.w = f2tf32(breg[r].w);
            *(uint4*)&Bs[(brow + r*8)*136 + bcol] = ub;
        }
        __syncthreads();

        if (k0 + GBK < K) {
            #pragma unroll
            for (int r = 0; r < 4; r++) {
                areg[r] = *(const float4*)&A[(size_t)(m0 + arow + r*32)*K + k0 + GBK + acol];
                breg[r] = *(const float4*)&Bm[(size_t)(brow + r*8)*N + k0 + GBK == 0 ? 0 : (size_t)(k0 + GBK + brow + r*8)*N + n0 + bcol];
            }
        }
        // NOTE: the B prefetch line above must index rows (k0+GBK+brow+r*8); rewrite cleanly:
        if (k0 + GBK < K) {
            #pragma unroll
            for (int r = 0; r < 4; r++) {
                areg[r] = *(const float4*)&A[(size_t)(m0 + arow + r*32)*K + (k0 + GBK) + acol];
                breg[r] = *(const float4*)&Bm[(size_t)((k0 + GBK) + brow + r*8)*N + n0 + bcol];
            }
        }

        #pragma unroll
        for (int ks = 0; ks < 4; ks++) {
            uint32_t a[4][4], b[4][2];
            #pragma unroll
            for (int mt = 0; mt < 4; mt++) {
                int row = wm + mt*16 + (lane >> 2);
                int col = ks*8 + (lane & 3);
                a[mt][0] = As[row*36 + col];
                a[mt][1] = As[(row+8)*36 + col];
                a[mt][2] = As[row*36 + col + 4];
                a[mt][3] = As[(row+8)*36 + col + 4];
            }
            #pragma unroll
            for (int nt = 0; nt < 4; nt++) {
                int kk = ks*8 + (lane & 3);
                int nn = wn + nt*8 + (lane >> 2);
                b[nt][0] = Bs[kk*136 + nn];
                b[nt][1] = Bs[(kk+4)*136 + nn];
            }
            #pragma unroll
            for (int mt = 0; mt < 4; mt++)
                #pragma unroll
                for (int nt = 0; nt < 4; nt++)
                    mma_tf32(c[mt][nt], a[mt], b[nt]);
        }
        __syncthreads();
    }

    // epilogue
    #pragma unroll
    for (int mt = 0; mt < 4; mt++) {
        #pragma unroll
        for (int half = 0; half < 2; half++) {
            int m = m0 + wm + mt*16 + (lane >> 2) + half*8;
            float bvv = bias ? bias[m] : 0.f;
            #pragma unroll
            for (int nt = 0; nt < 4; nt++) {
                int n = n0 + wn + nt*8 + 2*(lane & 3);
                float2 o;
                o.x = c[mt][nt][half*2 + 0] + bvv;
                o.y = c[mt][nt][half*2 + 1] + bvv;
                if (Rm) {
                    float2 r = *(const float2*)&Rm[(size_t)m*N + n];
                    o.x += r.x; o.y += r.y;
                }
                *(float2*)&Cm[(size_t)m*N + n] = o;
            }
        }
    }
}

// ---------------------------------------------------------------------------
// Flash attention with tf32 MMA. Block = 64 queries of one (b,h).
// 128 threads = 4 warps, warp owns 16 query rows. Q frags register-resident.
// Smem: Qs/Ps [64][68] (dual use), Ks [64][68], Vs [64][72]. 53248 B dynamic.
// ---------------------------------------------------------------------------
__global__ __launch_bounds__(128)
void attention_kernel(const float* __restrict__ qkv,
                      float* __restrict__ outp)
{
    extern __shared__ uint32_t smd[];
    uint32_t* Ps = smd;                 // [64][68] — Q staging, then P, then O out
    uint32_t* Ks = smd + 64*68;         // [64][68]  Ks[j][d]
    uint32_t* Vs = smd + 2*64*68;       // [64][72]  Vs[j][d]

    int bh = blockIdx.y;
    int bb = bh >> 3, hh = bh & 7;
    int i0 = blockIdx.x * 64;
    const float* qp = qkv + ((size_t)bb*3*CH + hh*HD) * HW_;
    const float* kp = qp + (size_t)CH * HW_;
    const float* vp = qp + (size_t)2*CH * HW_;

    int tid = threadIdx.x, lane = tid & 31, warp = tid >> 5;

    // stage Q (transpose to [i][d], tf32)
    #pragma unroll
    for (int e = 0; e < 32; e++) {
        int idx = e*128 + tid;
        int d = idx >> 6, i = idx & 63;
        Ps[i*68 + d] = f2tf32(qp[(size_t)d*HW_ + i0 + i]);
    }
    __syncthreads();

    // Q fragments, register resident: row block = warp*16
    uint32_t qf[8][4];
    {
        int row = warp*16 + (lane >> 2);
        #pragma unroll
        for (int ks = 0; ks < 8; ks++) {
            int col = ks*8 + (lane & 3);
            qf[ks][0] = Ps[row*68 + col];
            qf[ks][1] = Ps[(row+8)*68 + col];
            qf[ks][2] = Ps[row*68 + col + 4];
            qf[ks][3] = Ps[(row+8)*68 + col + 4];
        }
    }
    __syncthreads();

    float m0v = -1e30f, m1v = -1e30f, l0 = 0.f, l1 = 0.f;
    float o[8][4];
    #pragma unroll
    for (int dt = 0; dt < 8; dt++)
        #pragma unroll
        for (int e = 0; e < 4; e++) o[dt][e] = 0.f;

    for (int j0 = 0; j0 < HW_; j0 += 64) {
        __syncthreads();
        // load K, V tiles (transpose to [j][d], tf32)
        #pragma unroll
        for (int e = 0; e < 32; e++) {
            int idx = e*128 + tid;
            int d = idx >> 6, j = idx & 63;
            Ks[j*68 + d] = f2tf32(kp[(size_t)d*HW_ + j0 + j]);
            Vs[j*72 + d] = f2tf32(vp[(size_t)d*HW_ + j0 + j]);
        }
        __syncthreads();

        // S = Q K^T
        float s[8][4];
        #pragma unroll
        for (int nt = 0; nt < 8; nt++)
            #pragma unroll
            for (int e = 0; e < 4; e++) s[nt][e] = 0.f;

        #pragma unroll
        for (int ks = 0; ks < 8; ks++) {
            int kk = ks*8 + (lane & 3);
            #pragma unroll
            for (int nt = 0; nt < 8; nt++) {
                uint32_t b[2];
                int jj = nt*8 + (lane >> 2);
                b[0] = Ks[jj*68 + kk];
                b[1] = Ks[jj*68 + kk + 4];
                mma_tf32(s[nt], qf[ks], b);
            }
        }

        // online softmax: thread rows r0 = warp*16+lane/4, r1 = r0+8
        float rmax0 = -1e30f, rmax1 = -1e30f;
        #pragma unroll
        for (int nt = 0; nt < 8; nt++) {
            s[nt][0] *= SCALE_; s[nt][1] *= SCALE_;
            s[nt][2] *= SCALE_; s[nt][3] *= SCALE_;
            rmax0 = fmaxf(rmax0, fmaxf(s[nt][0], s[nt][1]));
            rmax1 = fmaxf(rmax1, fmaxf(s[nt][2], s[nt][3]));
        }
        #pragma unroll
        for (int off = 1; off < 4; off <<= 1) {
            rmax0 = fmaxf(rmax0, __shfl_xor_sync(0xffffffffu, rmax0, off));
            rmax1 = fmaxf(rmax1, __shfl_xor_sync(0xffffffffu, rmax1, off));
        }
        float mn0 = fmaxf(m0v, rmax0), mn1 = fmaxf(m1v, rmax1);
        float corr0 = __expf(m0v - mn0), corr1 = __expf(m1v - mn1);
        m0v = mn0; m1v = mn1;

        float rs0 = 0.f, rs1 = 0.f;
        #pragma unroll
        for (int nt = 0; nt < 8; nt++) {
            s[nt][0] = __expf(s[nt][0] - mn0);
            s[nt][1] = __expf(s[nt][1] - mn0);
            s[nt][2] = __expf(s[nt][2] - mn1);
            s[nt][3] = __expf(s[nt][3] - mn1);
            rs0 += s[nt][0] + s[nt][1];
            rs1 += s[nt][2] + s[nt][3];
        }
        #pragma unroll
        for (int off = 1; off < 4; off <<= 1) {
            rs0 += __shfl_xor_sync(0xffffffffu, rs0, off);
            rs1 += __shfl_xor_sync(0xffffffffu, rs1, off);
        }
        l0 = l0*corr0 + rs0;
        l1 = l1*corr1 + rs1;
        #pragma unroll
        for (int dt = 0; dt < 8; dt++) {
            o[dt][0] *= corr0; o[dt][1] *= corr0;
            o[dt][2] *= corr1; o[dt][3] *= corr1;
        }

        // write P (tf32) to smem for A-frag reload
        {
            int r0 = warp*16 + (lane >> 2);
            #pragma unroll
            for (int nt = 0; nt < 8; nt++) {
                int col = nt*8 + 2*(lane & 3);
                uint2 p0, p1;
                p0.x = f2tf32(s[nt][0]); p0.y = f2tf32(s[nt][1]);
                p1.x = f2tf32(s[nt][2]); p1.y = f2tf32(s[nt][3]);
                *(uint2*)&Ps[r0*68 + col]     = p0;
                *(uint2*)&Ps[(r0+8)*68 + col] = p1;
            }
        }
        __syncthreads();

        // O += P @ V
        #pragma unroll
        for (int ks = 0; ks < 8; ks++) {
            uint32_t pa[4];
            int row = warp*16 + (lane >> 2);
            int col = ks*8 + (lane & 3);
            pa[0] = Ps[row*68 + col];
            pa[1] = Ps[(row+8)*68 + col];
            pa[2] = Ps[row*68 + col + 4];
            pa[3] = Ps[(row+8)*68 + col + 4];
            int jj = ks*8 + (lane & 3);
            #pragma unroll
            for (int dt = 0; dt < 8; dt++) {
                uint32_t b[2];
                int dd = dt*8 + (lane >> 2);
                b[0] = Vs[jj*72 + dd];
                b[1] = Vs[(jj+4)*72 + dd];
                mma_tf32(o[dt], pa, b);
            }
        }
    }

    __syncthreads();
    // normalize, stage O (fp32) into Ps buffer as [i][d]
    {
        float* PsF = (float*)Ps;
        float inv0 = 1.f / l0, inv1 = 1.f / l1;
        int r0 = warp*16 + (lane >> 2);
        #pragma unroll
        for (int dt = 0; dt < 8; dt++) {
            int col = dt*8 + 2*(lane & 3);
            float2 v0, v1;
            v0.x = o[dt][0]*inv0; v0.y = o[dt][1]*inv0;
            v1.x = o[dt][2]*inv1; v1.y = o[dt][3]*inv1;
            *(float2*)&PsF[r0*68 + col]     = v0;
            *(float2*)&PsF[(r0+8)*68 + col] = v1;
        }
    }
    __syncthreads();

    // coalesced store out[d][i]
    float* ob = outp + ((size_t)bb*CH + hh*HD) * HW_;
    const float* PsF = (const float*)Ps;
    #pragma unroll
    for (int e = 0; e < 32; e++) {
        int idx = e*128 + tid;
        int d = idx >> 6, i = idx & 63;
        ob[(size_t)d*HW_ + i0 + i] = PsF[i*68 + d];
    }
}

// ---------------------------------------------------------------------------
extern "C" void kernel_launch(void* const* d_in, const int* in_sizes, int n_in,
                              void* d_out, int out_size)
{
    const float* x      = (const float*)d_in[0];
    const float* gn_w   = (const float*)d_in[1];
    const float* gn_b   = (const float*)d_in[2];
    const float* qkv_w  = (const float*)d_in[3];
    const float* qkv_b  = (const float*)d_in[4];
    const float* proj_w = (const float*)d_in[5];
    const float* proj_b = (const float*)d_in[6];
    float* out = (float*)d_out;

    float *xn, *qkvb, *att;
    cudaGetSymbolAddress((void**)&xn,   g_xn);
    cudaGetSymbolAddress((void**)&qkvb, g_qkv);
    cudaGetSymbolAddress((void**)&att,  g_att);

    const int ATT_SMEM = (64*68*2 + 64*72) * 4;  // 53248 B
    cudaFuncSetAttribute(attention_kernel,
                         cudaFuncAttributeMaxDynamicSharedMemorySize, ATT_SMEM);

    groupnorm_kernel<<<BATCH*NGROUPS, 256>>>(x, gn_w, gn_b, xn);

    mma_gemm_kernel<<<dim3(HW_/GBN, (3*CH)/GBM, BATCH), 256>>>(
        qkv_w, xn, qkvb, qkv_b, (const float*)0, 3*CH, CH, HW_);

    attention_kernel<<<dim3(HW_/64, BATCH*NH), 128, ATT_SMEM>>>(qkvb, att);

    mma_gemm_kernel<<<dim3(HW_/GBN, CH/GBM, BATCH), 256>>>(
        proj_w, att, out, proj_b, x, CH, CH, HW_);
}